// round 4
// baseline (speedup 1.0000x reference)
#include <cuda_runtime.h>
#include <cuda_bf16.h>
#include <math.h>

// Problem constants (from reference setup_inputs)
#define NMAX   50000
#define EMAX   800000
#define DIN    256
#define HEADS  4
#define DOUT   64
#define DFT    256            // HEADS*DOUT, also == DIN here
#define NEG_SLOPE 0.2f

// ---- scratch (allocation-free rule: __device__ globals) ----
__device__ float g_ft[NMAX * DFT];     // projected features [N, H*D]
__device__ float g_el[NMAX * HEADS];   // attn_l dot per node/head
__device__ float g_er[NMAX * HEADS];   // attn_r dot per node/head
__device__ int   g_off[NMAX + 1];      // CSR offsets into sorted dst

// ============================================================
// Kernel 1: ft = feat @ W   (M=N, K=256, Ncols=256), fp32
// 128x128 block tile, BK=16, 8x8 per-thread microtile, 256 thr,
// register prefetch of the next global tile.
// ============================================================
#define GM 128
#define GN 128
#define GK 16
#define GMP (GM + 4)   // padded A^T row to reduce store conflicts

__global__ __launch_bounds__(256) void gemm_ft_kernel(
    const float* __restrict__ feat, const float* __restrict__ W, int N)
{
    __shared__ float As[GK][GMP];  // A transposed: As[k][m]
    __shared__ float Bs[GK][GN];   // Bs[k][n]

    const int tid = threadIdx.x;
    const int m0 = blockIdx.x * GM;
    const int n0 = blockIdx.y * GN;

    // A-load mapping: 128 rows x 16 cols; each thread 2 float4
    const int ar = tid >> 2;           // 0..63 (and +64)
    const int ac = (tid & 3) << 2;     // 0,4,8,12
    // B-load mapping: 16 rows x 128 cols; each thread 2 float4
    const int br = tid >> 5;           // 0..7 (and +8)
    const int bc = (tid & 31) << 2;    // 0..124

    const int tx = tid & 15;           // 0..15
    const int ty = tid >> 4;           // 0..15
    const int mrow = ty * 8;
    const int ncol = tx * 8;

    float acc[8][8];
#pragma unroll
    for (int i = 0; i < 8; i++)
#pragma unroll
        for (int j = 0; j < 8; j++) acc[i][j] = 0.f;

    const int r0 = m0 + ar;
    const int r1 = m0 + ar + 64;

    // prefetch tile 0
    float4 pa0 = make_float4(0.f,0.f,0.f,0.f), pa1 = pa0;
    if (r0 < N) pa0 = *(const float4*)(feat + (size_t)r0 * DIN + ac);
    if (r1 < N) pa1 = *(const float4*)(feat + (size_t)r1 * DIN + ac);
    float4 pb0 = *(const float4*)(W + (size_t)br * DFT + n0 + bc);
    float4 pb1 = *(const float4*)(W + (size_t)(br + 8) * DFT + n0 + bc);

    for (int k0 = 0; k0 < DIN; k0 += GK) {
        // commit prefetched tile to smem (A transposed)
        As[ac + 0][ar] = pa0.x;  As[ac + 1][ar] = pa0.y;
        As[ac + 2][ar] = pa0.z;  As[ac + 3][ar] = pa0.w;
        As[ac + 0][ar + 64] = pa1.x;  As[ac + 1][ar + 64] = pa1.y;
        As[ac + 2][ar + 64] = pa1.z;  As[ac + 3][ar + 64] = pa1.w;
        *(float4*)&Bs[br][bc]     = pb0;
        *(float4*)&Bs[br + 8][bc] = pb1;
        __syncthreads();

        // prefetch next tile
        const int kn = k0 + GK;
        if (kn < DIN) {
            pa0 = make_float4(0.f,0.f,0.f,0.f); pa1 = pa0;
            if (r0 < N) pa0 = *(const float4*)(feat + (size_t)r0 * DIN + kn + ac);
            if (r1 < N) pa1 = *(const float4*)(feat + (size_t)r1 * DIN + kn + ac);
            pb0 = *(const float4*)(W + (size_t)(kn + br) * DFT + n0 + bc);
            pb1 = *(const float4*)(W + (size_t)(kn + br + 8) * DFT + n0 + bc);
        }

#pragma unroll
        for (int k = 0; k < GK; k++) {
            const float4 a0 = *(const float4*)&As[k][mrow];
            const float4 a1 = *(const float4*)&As[k][mrow + 4];
            const float4 b0 = *(const float4*)&Bs[k][ncol];
            const float4 b1 = *(const float4*)&Bs[k][ncol + 4];
            const float am[8] = {a0.x,a0.y,a0.z,a0.w,a1.x,a1.y,a1.z,a1.w};
            const float bn[8] = {b0.x,b0.y,b0.z,b0.w,b1.x,b1.y,b1.z,b1.w};
#pragma unroll
            for (int i = 0; i < 8; i++)
#pragma unroll
                for (int j = 0; j < 8; j++)
                    acc[i][j] = fmaf(am[i], bn[j], acc[i][j]);
        }
        __syncthreads();
    }

#pragma unroll
    for (int i = 0; i < 8; i++) {
        const int row = m0 + mrow + i;
        if (row < N) {
            *(float4*)(g_ft + (size_t)row * DFT + n0 + ncol) =
                make_float4(acc[i][0], acc[i][1], acc[i][2], acc[i][3]);
            *(float4*)(g_ft + (size_t)row * DFT + n0 + ncol + 4) =
                make_float4(acc[i][4], acc[i][5], acc[i][6], acc[i][7]);
        }
    }
}

// ============================================================
// Kernel 2: el[n,h] = sum_d ft[n,h,d]*attn_l[h,d]; er likewise
// ============================================================
__global__ __launch_bounds__(256) void elr_kernel(
    const float* __restrict__ attn_l, const float* __restrict__ attn_r)
{
    const int n = blockIdx.x;
    const int t = threadIdx.x;
    const float v = g_ft[(size_t)n * DFT + t];
    float pl = v * attn_l[t];
    float pr = v * attn_r[t];
#pragma unroll
    for (int o = 16; o; o >>= 1) {
        pl += __shfl_xor_sync(0xffffffffu, pl, o);
        pr += __shfl_xor_sync(0xffffffffu, pr, o);
    }
    __shared__ float sl[8], sr[8];
    const int w = t >> 5;
    if ((t & 31) == 0) { sl[w] = pl; sr[w] = pr; }
    __syncthreads();
    if (t < HEADS) {
        g_el[n * HEADS + t] = sl[2 * t] + sl[2 * t + 1];
        g_er[n * HEADS + t] = sr[2 * t] + sr[2 * t + 1];
    }
}

// ============================================================
// Kernel 3: CSR offsets from sorted dst.
// ============================================================
__global__ void build_off_kernel(const int* __restrict__ dst, int E, int N)
{
    const int i = blockIdx.x * blockDim.x + threadIdx.x;
    if (i >= E) return;
    const int d  = dst[i];
    const int dp = (i == 0) ? -1 : dst[i - 1];
    for (int x = dp + 1; x <= d; x++) g_off[x] = i;
    if (i == E - 1) {
        for (int x = d + 1; x <= N; x++) g_off[x] = E;
    }
}

// ============================================================
// Kernel 4: fused segment softmax + weighted gather-aggregate.
// 64-thread CTA per dst node; thread t owns channels [4t,4t+4)
// -> one LDG.128 + 4 FFMA per edge per thread.
// ============================================================
__device__ __forceinline__ float leaky(float x) {
    return x > 0.f ? x : NEG_SLOPE * x;
}

#define ACH 64   // edges staged per pass

__global__ __launch_bounds__(64) void agg_kernel(
    const int* __restrict__ src, float* __restrict__ out)
{
    const int n = blockIdx.x;
    const int t = threadIdx.x;
    __shared__ float s_er[HEADS], s_m[HEADS], s_is[HEADS];
    __shared__ int   s_src[ACH];
    __shared__ float s_a[ACH][HEADS];

    const int begin = g_off[n];
    const int end   = g_off[n + 1];

    if (t < HEADS) s_er[t] = g_er[n * HEADS + t];
    __syncthreads();

    if (t < 32) {
        const float e0r = s_er[0], e1r = s_er[1], e2r = s_er[2], e3r = s_er[3];
        float m0 = -1e30f, m1 = -1e30f, m2 = -1e30f, m3 = -1e30f;
        for (int k = begin + t; k < end; k += 32) {
            const int s = src[k];
            const float4 ev = *(const float4*)(g_el + (size_t)s * HEADS);
            m0 = fmaxf(m0, leaky(ev.x + e0r));
            m1 = fmaxf(m1, leaky(ev.y + e1r));
            m2 = fmaxf(m2, leaky(ev.z + e2r));
            m3 = fmaxf(m3, leaky(ev.w + e3r));
        }
#pragma unroll
        for (int o = 16; o; o >>= 1) {
            m0 = fmaxf(m0, __shfl_xor_sync(0xffffffffu, m0, o));
            m1 = fmaxf(m1, __shfl_xor_sync(0xffffffffu, m1, o));
            m2 = fmaxf(m2, __shfl_xor_sync(0xffffffffu, m2, o));
            m3 = fmaxf(m3, __shfl_xor_sync(0xffffffffu, m3, o));
        }
        float s0 = 0.f, s1 = 0.f, s2 = 0.f, s3 = 0.f;
        for (int k = begin + t; k < end; k += 32) {
            const int s = src[k];
            const float4 ev = *(const float4*)(g_el + (size_t)s * HEADS);
            s0 += __expf(leaky(ev.x + e0r) - m0);
            s1 += __expf(leaky(ev.y + e1r) - m1);
            s2 += __expf(leaky(ev.z + e2r) - m2);
            s3 += __expf(leaky(ev.w + e3r) - m3);
        }
#pragma unroll
        for (int o = 16; o; o >>= 1) {
            s0 += __shfl_xor_sync(0xffffffffu, s0, o);
            s1 += __shfl_xor_sync(0xffffffffu, s1, o);
            s2 += __shfl_xor_sync(0xffffffffu, s2, o);
            s3 += __shfl_xor_sync(0xffffffffu, s3, o);
        }
        if (t == 0) {
            s_m[0] = m0; s_m[1] = m1; s_m[2] = m2; s_m[3] = m3;
            s_is[0] = 1.f / s0; s_is[1] = 1.f / s1;
            s_is[2] = 1.f / s2; s_is[3] = 1.f / s3;
        }
    }
    __syncthreads();

    const int h = t >> 4;                 // head of channels 4t..4t+3
    float4 acc = make_float4(0.f, 0.f, 0.f, 0.f);

    for (int c0 = begin; c0 < end; c0 += ACH) {
        const int cnt = min(ACH, end - c0);
        if (t < cnt) {
            const int s = src[c0 + t];
            s_src[t] = s;
            const float4 ev = *(const float4*)(g_el + (size_t)s * HEADS);
            s_a[t][0] = __expf(leaky(ev.x + s_er[0]) - s_m[0]) * s_is[0];
            s_a[t][1] = __expf(leaky(ev.y + s_er[1]) - s_m[1]) * s_is[1];
            s_a[t][2] = __expf(leaky(ev.z + s_er[2]) - s_m[2]) * s_is[2];
            s_a[t][3] = __expf(leaky(ev.w + s_er[3]) - s_m[3]) * s_is[3];
        }
        __syncthreads();
#pragma unroll 4
        for (int kk = 0; kk < cnt; kk++) {
            const int s = s_src[kk];
            const float a = s_a[kk][h];
            const float4 v = *(const float4*)(g_ft + (size_t)s * DFT + t * 4);
            acc.x = fmaf(a, v.x, acc.x);
            acc.y = fmaf(a, v.y, acc.y);
            acc.z = fmaf(a, v.z, acc.z);
            acc.w = fmaf(a, v.w, acc.w);
        }
        __syncthreads();
    }
    *(float4*)(out + (size_t)n * DFT + t * 4) = acc;
}

// ============================================================
extern "C" void kernel_launch(void* const* d_in, const int* in_sizes, int n_in,
                              void* d_out, int out_size)
{
    const float* feat   = (const float*)d_in[0];
    const int*   src    = (const int*)  d_in[1];
    const int*   dst    = (const int*)  d_in[2];
    const float* W      = (const float*)d_in[3];
    const float* attn_l = (const float*)d_in[4];
    const float* attn_r = (const float*)d_in[5];
    float* out = (float*)d_out;

    int N = in_sizes[0] / DIN;
    int E = in_sizes[1];
    if (N > NMAX) N = NMAX;
    if (E > EMAX) E = EMAX;

    dim3 ggrid((N + GM - 1) / GM, DFT / GN);
    gemm_ft_kernel<<<ggrid, 256>>>(feat, W, N);
    elr_kernel<<<N, 256>>>(attn_l, attn_r);
    build_off_kernel<<<(E + 255) / 256, 256>>>(dst, E, N);
    agg_kernel<<<N, 64>>>(src, out);
}

// round 5
// speedup vs baseline: 1.0013x; 1.0013x over previous
#include <cuda_runtime.h>
#include <cuda_bf16.h>
#include <math.h>

// Problem constants (from reference setup_inputs)
#define NMAX   50000
#define EMAX   800000
#define DIN    256
#define HEADS  4
#define DOUT   64
#define DFT    256            // HEADS*DOUT, also == DIN here
#define NEG_SLOPE 0.2f

// ---- scratch (allocation-free rule: __device__ globals) ----
__device__ float g_ft[NMAX * DFT];     // projected features [N, H*D]
__device__ float g_el[NMAX * HEADS];   // attn_l dot per node/head
__device__ float g_er[NMAX * HEADS];   // attn_r dot per node/head
__device__ int   g_off[NMAX + 1];      // CSR offsets into sorted dst

// ============================================================
// Kernel 1: ft = feat @ W   (M=N, K=256, Ncols=256), fp32
// 128x128 block tile, BK=16, 8x8 per-thread microtile, 256 thr,
// register prefetch of the next global tile.
// ============================================================
#define GM 128
#define GN 128
#define GK 16
#define GMP (GM + 4)   // padded A^T row to reduce store conflicts

__global__ __launch_bounds__(256) void gemm_ft_kernel(
    const float* __restrict__ feat, const float* __restrict__ W, int N)
{
    __shared__ float As[GK][GMP];  // A transposed: As[k][m]
    __shared__ float Bs[GK][GN];   // Bs[k][n]

    const int tid = threadIdx.x;
    const int m0 = blockIdx.x * GM;
    const int n0 = blockIdx.y * GN;

    // A-load mapping: 128 rows x 16 cols; each thread 2 float4
    const int ar = tid >> 2;           // 0..63 (and +64)
    const int ac = (tid & 3) << 2;     // 0,4,8,12
    // B-load mapping: 16 rows x 128 cols; each thread 2 float4
    const int br = tid >> 5;           // 0..7 (and +8)
    const int bc = (tid & 31) << 2;    // 0..124

    const int tx = tid & 15;           // 0..15
    const int ty = tid >> 4;           // 0..15
    const int mrow = ty * 8;
    const int ncol = tx * 8;

    float acc[8][8];
#pragma unroll
    for (int i = 0; i < 8; i++)
#pragma unroll
        for (int j = 0; j < 8; j++) acc[i][j] = 0.f;

    const int r0 = m0 + ar;
    const int r1 = m0 + ar + 64;

    // prefetch tile 0
    float4 pa0 = make_float4(0.f,0.f,0.f,0.f), pa1 = pa0;
    if (r0 < N) pa0 = *(const float4*)(feat + (size_t)r0 * DIN + ac);
    if (r1 < N) pa1 = *(const float4*)(feat + (size_t)r1 * DIN + ac);
    float4 pb0 = *(const float4*)(W + (size_t)br * DFT + n0 + bc);
    float4 pb1 = *(const float4*)(W + (size_t)(br + 8) * DFT + n0 + bc);

    for (int k0 = 0; k0 < DIN; k0 += GK) {
        // commit prefetched tile to smem (A transposed)
        As[ac + 0][ar] = pa0.x;  As[ac + 1][ar] = pa0.y;
        As[ac + 2][ar] = pa0.z;  As[ac + 3][ar] = pa0.w;
        As[ac + 0][ar + 64] = pa1.x;  As[ac + 1][ar + 64] = pa1.y;
        As[ac + 2][ar + 64] = pa1.z;  As[ac + 3][ar + 64] = pa1.w;
        *(float4*)&Bs[br][bc]     = pb0;
        *(float4*)&Bs[br + 8][bc] = pb1;
        __syncthreads();

        // prefetch next tile
        const int kn = k0 + GK;
        if (kn < DIN) {
            pa0 = make_float4(0.f,0.f,0.f,0.f); pa1 = pa0;
            if (r0 < N) pa0 = *(const float4*)(feat + (size_t)r0 * DIN + kn + ac);
            if (r1 < N) pa1 = *(const float4*)(feat + (size_t)r1 * DIN + kn + ac);
            pb0 = *(const float4*)(W + (size_t)(kn + br) * DFT + n0 + bc);
            pb1 = *(const float4*)(W + (size_t)(kn + br + 8) * DFT + n0 + bc);
        }

#pragma unroll
        for (int k = 0; k < GK; k++) {
            const float4 a0 = *(const float4*)&As[k][mrow];
            const float4 a1 = *(const float4*)&As[k][mrow + 4];
            const float4 b0 = *(const float4*)&Bs[k][ncol];
            const float4 b1 = *(const float4*)&Bs[k][ncol + 4];
            const float am[8] = {a0.x,a0.y,a0.z,a0.w,a1.x,a1.y,a1.z,a1.w};
            const float bn[8] = {b0.x,b0.y,b0.z,b0.w,b1.x,b1.y,b1.z,b1.w};
#pragma unroll
            for (int i = 0; i < 8; i++)
#pragma unroll
                for (int j = 0; j < 8; j++)
                    acc[i][j] = fmaf(am[i], bn[j], acc[i][j]);
        }
        __syncthreads();
    }

#pragma unroll
    for (int i = 0; i < 8; i++) {
        const int row = m0 + mrow + i;
        if (row < N) {
            *(float4*)(g_ft + (size_t)row * DFT + n0 + ncol) =
                make_float4(acc[i][0], acc[i][1], acc[i][2], acc[i][3]);
            *(float4*)(g_ft + (size_t)row * DFT + n0 + ncol + 4) =
                make_float4(acc[i][4], acc[i][5], acc[i][6], acc[i][7]);
        }
    }
}

// ============================================================
// Kernel 2: el[n,h] = sum_d ft[n,h,d]*attn_l[h,d]; er likewise
// ============================================================
__global__ __launch_bounds__(256) void elr_kernel(
    const float* __restrict__ attn_l, const float* __restrict__ attn_r)
{
    const int n = blockIdx.x;
    const int t = threadIdx.x;
    const float v = g_ft[(size_t)n * DFT + t];
    float pl = v * attn_l[t];
    float pr = v * attn_r[t];
#pragma unroll
    for (int o = 16; o; o >>= 1) {
        pl += __shfl_xor_sync(0xffffffffu, pl, o);
        pr += __shfl_xor_sync(0xffffffffu, pr, o);
    }
    __shared__ float sl[8], sr[8];
    const int w = t >> 5;
    if ((t & 31) == 0) { sl[w] = pl; sr[w] = pr; }
    __syncthreads();
    if (t < HEADS) {
        g_el[n * HEADS + t] = sl[2 * t] + sl[2 * t + 1];
        g_er[n * HEADS + t] = sr[2 * t] + sr[2 * t + 1];
    }
}

// ============================================================
// Kernel 3: CSR offsets from sorted dst.
// ============================================================
__global__ void build_off_kernel(const int* __restrict__ dst, int E, int N)
{
    const int i = blockIdx.x * blockDim.x + threadIdx.x;
    if (i >= E) return;
    const int d  = dst[i];
    const int dp = (i == 0) ? -1 : dst[i - 1];
    for (int x = dp + 1; x <= d; x++) g_off[x] = i;
    if (i == E - 1) {
        for (int x = d + 1; x <= N; x++) g_off[x] = E;
    }
}

// ============================================================
// Kernel 4: fused segment softmax + weighted gather-aggregate.
// 64-thread CTA per dst node; thread t owns channels [4t,4t+4)
// -> one LDG.128 + 4 FFMA per edge per thread.
// ============================================================
__device__ __forceinline__ float leaky(float x) {
    return x > 0.f ? x : NEG_SLOPE * x;
}

#define ACH 64   // edges staged per pass

__global__ __launch_bounds__(64) void agg_kernel(
    const int* __restrict__ src, float* __restrict__ out)
{
    const int n = blockIdx.x;
    const int t = threadIdx.x;
    __shared__ float s_er[HEADS], s_m[HEADS], s_is[HEADS];
    __shared__ int   s_src[ACH];
    __shared__ float s_a[ACH][HEADS];

    const int begin = g_off[n];
    const int end   = g_off[n + 1];

    if (t < HEADS) s_er[t] = g_er[n * HEADS + t];
    __syncthreads();

    if (t < 32) {
        const float e0r = s_er[0], e1r = s_er[1], e2r = s_er[2], e3r = s_er[3];
        float m0 = -1e30f, m1 = -1e30f, m2 = -1e30f, m3 = -1e30f;
        for (int k = begin + t; k < end; k += 32) {
            const int s = src[k];
            const float4 ev = *(const float4*)(g_el + (size_t)s * HEADS);
            m0 = fmaxf(m0, leaky(ev.x + e0r));
            m1 = fmaxf(m1, leaky(ev.y + e1r));
            m2 = fmaxf(m2, leaky(ev.z + e2r));
            m3 = fmaxf(m3, leaky(ev.w + e3r));
        }
#pragma unroll
        for (int o = 16; o; o >>= 1) {
            m0 = fmaxf(m0, __shfl_xor_sync(0xffffffffu, m0, o));
            m1 = fmaxf(m1, __shfl_xor_sync(0xffffffffu, m1, o));
            m2 = fmaxf(m2, __shfl_xor_sync(0xffffffffu, m2, o));
            m3 = fmaxf(m3, __shfl_xor_sync(0xffffffffu, m3, o));
        }
        float s0 = 0.f, s1 = 0.f, s2 = 0.f, s3 = 0.f;
        for (int k = begin + t; k < end; k += 32) {
            const int s = src[k];
            const float4 ev = *(const float4*)(g_el + (size_t)s * HEADS);
            s0 += __expf(leaky(ev.x + e0r) - m0);
            s1 += __expf(leaky(ev.y + e1r) - m1);
            s2 += __expf(leaky(ev.z + e2r) - m2);
            s3 += __expf(leaky(ev.w + e3r) - m3);
        }
#pragma unroll
        for (int o = 16; o; o >>= 1) {
            s0 += __shfl_xor_sync(0xffffffffu, s0, o);
            s1 += __shfl_xor_sync(0xffffffffu, s1, o);
            s2 += __shfl_xor_sync(0xffffffffu, s2, o);
            s3 += __shfl_xor_sync(0xffffffffu, s3, o);
        }
        if (t == 0) {
            s_m[0] = m0; s_m[1] = m1; s_m[2] = m2; s_m[3] = m3;
            s_is[0] = 1.f / s0; s_is[1] = 1.f / s1;
            s_is[2] = 1.f / s2; s_is[3] = 1.f / s3;
        }
    }
    __syncthreads();

    const int h = t >> 4;                 // head of channels 4t..4t+3
    float4 acc = make_float4(0.f, 0.f, 0.f, 0.f);

    for (int c0 = begin; c0 < end; c0 += ACH) {
        const int cnt = min(ACH, end - c0);
        if (t < cnt) {
            const int s = src[c0 + t];
            s_src[t] = s;
            const float4 ev = *(const float4*)(g_el + (size_t)s * HEADS);
            s_a[t][0] = __expf(leaky(ev.x + s_er[0]) - s_m[0]) * s_is[0];
            s_a[t][1] = __expf(leaky(ev.y + s_er[1]) - s_m[1]) * s_is[1];
            s_a[t][2] = __expf(leaky(ev.z + s_er[2]) - s_m[2]) * s_is[2];
            s_a[t][3] = __expf(leaky(ev.w + s_er[3]) - s_m[3]) * s_is[3];
        }
        __syncthreads();
#pragma unroll 4
        for (int kk = 0; kk < cnt; kk++) {
            const int s = s_src[kk];
            const float a = s_a[kk][h];
            const float4 v = *(const float4*)(g_ft + (size_t)s * DFT + t * 4);
            acc.x = fmaf(a, v.x, acc.x);
            acc.y = fmaf(a, v.y, acc.y);
            acc.z = fmaf(a, v.z, acc.z);
            acc.w = fmaf(a, v.w, acc.w);
        }
        __syncthreads();
    }
    *(float4*)(out + (size_t)n * DFT + t * 4) = acc;
}

// ============================================================
extern "C" void kernel_launch(void* const* d_in, const int* in_sizes, int n_in,
                              void* d_out, int out_size)
{
    const float* feat   = (const float*)d_in[0];
    const int*   src    = (const int*)  d_in[1];
    const int*   dst    = (const int*)  d_in[2];
    const float* W      = (const float*)d_in[3];
    const float* attn_l = (const float*)d_in[4];
    const float* attn_r = (const float*)d_in[5];
    float* out = (float*)d_out;

    int N = in_sizes[0] / DIN;
    int E = in_sizes[1];
    if (N > NMAX) N = NMAX;
    if (E > EMAX) E = EMAX;

    dim3 ggrid((N + GM - 1) / GM, DFT / GN);
    gemm_ft_kernel<<<ggrid, 256>>>(feat, W, N);
    elr_kernel<<<N, 256>>>(attn_l, attn_r);
    build_off_kernel<<<(E + 255) / 256, 256>>>(dst, E, N);
    agg_kernel<<<N, 64>>>(src, out);
}